// round 16
// baseline (speedup 1.0000x reference)
#include <cuda_runtime.h>
#include <cuda_bf16.h>
#include <math.h>
#include <stdint.h>

#define MTOK 16384
#define DMODEL 256
#define FFDIM 1024
#define NHEAD 8
#define HDIM 32
#define SEQ 512
#define NLAYER 3
#define QKVN 768

// ---------------- scratch (device globals; no allocation allowed) ------------
__device__ float g_h  [MTOK * DMODEL];
__device__ uint16_t g_qkvh[MTOK * QKVN];
__device__ uint16_t g_ahi[MTOK * DMODEL];
__device__ uint16_t g_alo[MTOK * DMODEL];
__device__ uint16_t g_bhi[MTOK * FFDIM];
__device__ uint16_t g_blo[MTOK * FFDIM];
#define WPL 786432
__device__ uint16_t g_whi[3 * WPL];
__device__ uint16_t g_wlo[3 * WPL];
__device__ float g_bqkv[3 * QKVN];

__device__ __forceinline__ uint32_t smem_to_u32(const void* p) {
    uint32_t a;
    asm("{ .reg .u64 t; cvta.to.shared.u64 t, %1; cvt.u32.u64 %0, t; }"
        : "=r"(a) : "l"(p));
    return a;
}
__device__ __forceinline__ void ldsm_x4(uint32_t* r, uint32_t addr) {
    asm volatile("ldmatrix.sync.aligned.m8n8.x4.shared.b16 {%0,%1,%2,%3}, [%4];"
                 : "=r"(r[0]), "=r"(r[1]), "=r"(r[2]), "=r"(r[3]) : "r"(addr));
}
__device__ __forceinline__ void mma16816(float* c, const uint32_t* a,
                                         const uint32_t* b) {
    asm volatile(
        "mma.sync.aligned.m16n8k16.row.col.f32.bf16.bf16.f32 "
        "{%0,%1,%2,%3}, {%4,%5,%6,%7}, {%8,%9}, {%0,%1,%2,%3};"
        : "+f"(c[0]), "+f"(c[1]), "+f"(c[2]), "+f"(c[3])
        : "r"(a[0]), "r"(a[1]), "r"(a[2]), "r"(a[3]), "r"(b[0]), "r"(b[1]));
}
__device__ __forceinline__ uint32_t packbf(float lo, float hi) {
    uint32_t r;
    asm("cvt.rn.bf16x2.f32 %0, %1, %2;" : "=r"(r) : "f"(hi), "f"(lo));
    return r;
}
__device__ __forceinline__ void split2(float a, float b,
                                       uint32_t& hi, uint32_t& lo) {
    __nv_bfloat16 ha = __float2bfloat16(a);
    __nv_bfloat16 hb = __float2bfloat16(b);
    float ra = a - __bfloat162float(ha);
    float rb = b - __bfloat162float(hb);
    hi = (uint32_t)__bfloat16_as_ushort(ha) |
         ((uint32_t)__bfloat16_as_ushort(hb) << 16);
    __nv_bfloat16 la = __float2bfloat16(ra);
    __nv_bfloat16 lb = __float2bfloat16(rb);
    lo = (uint32_t)__bfloat16_as_ushort(la) |
         ((uint32_t)__bfloat16_as_ushort(lb) << 16);
}
__device__ __forceinline__ void cp16(uint32_t saddr, const void* g) {
    asm volatile("cp.async.cg.shared.global [%0], [%1], 16;"
                 :: "r"(saddr), "l"(g));
}

// ================= HMMA GEMM: C = A@B^T + bias (opt relu) ===================
// prods=1: ah*bh. prods=2: ah*bh + ah*bl. prods=3: + al*bh (fp32 emulation).
#define STRIDE_E 40
#define ARR_BYTES (128 * STRIDE_E * 2)
#define STAGE_BYTES (4 * ARR_BYTES)
#define HG_SMEM (2 * STAGE_BYTES)

__global__ __launch_bounds__(256, 2) void hgemm_kernel(
    const uint16_t* __restrict__ Ahi, const uint16_t* __restrict__ Alo,
    const uint16_t* __restrict__ Bhi, const uint16_t* __restrict__ Blo,
    const float* __restrict__ bias, float* __restrict__ C,
    uint16_t* __restrict__ Chi, uint16_t* __restrict__ Clo,
    int M, int N, int K, int relu, int prods)
{
    extern __shared__ char smem[];
    const uint32_t smb = smem_to_u32(smem);
    const int tid = threadIdx.x, wid = tid >> 5, lane = tid & 31;
    const int warp_m = wid & 3, warp_n = wid >> 2;
    const int rowBase = blockIdx.y * 128, colBase = blockIdx.x * 128;
    const bool pA = (prods >= 3), pB = (prods >= 2);

    const uint16_t* srcs[4] = {
        Ahi + (size_t)rowBase * K, Alo + (size_t)rowBase * K,
        Bhi + (size_t)colBase * K, Blo + (size_t)colBase * K };

    const int r0 = tid >> 2, s0 = (tid & 3);

    float acc[2][8][4];
#pragma unroll
    for (int f = 0; f < 2; f++)
#pragma unroll
        for (int j = 0; j < 8; j++)
#pragma unroll
            for (int e = 0; e < 4; e++) acc[f][j][e] = 0.f;

    const int nchunks = K >> 5;

    {
#pragma unroll
        for (int t = 0; t < 4; t++) {
            if (t == 1 && !pA) continue;
            if (t == 3 && !pB) continue;
            const uint16_t* s = srcs[t] + s0 * 8;
            uint32_t d = smb + t * ARR_BYTES + s0 * 16;
            cp16(d + r0 * 80, s + (size_t)r0 * K);
            cp16(d + (r0 + 64) * 80, s + (size_t)(r0 + 64) * K);
        }
    }
    asm volatile("cp.async.commit_group;" ::: "memory");

    const int a_mrow = (lane & 7) + ((lane >> 3) & 1) * 8;
    const int a_kcol = ((lane >> 4) & 1) * 8;
    const int bx_row = (lane & 7) + ((lane >> 4) & 1) * 8;
    const int bx_k   = ((lane >> 3) & 1) * 8;

    for (int c = 0; c < nchunks; c++) {
        if (c + 1 < nchunks) {
            const int co = (c + 1) * 32;
            const uint32_t stg = smb + ((c + 1) & 1) * STAGE_BYTES;
#pragma unroll
            for (int t = 0; t < 4; t++) {
                if (t == 1 && !pA) continue;
                if (t == 3 && !pB) continue;
                const uint16_t* s = srcs[t] + co + s0 * 8;
                uint32_t d = stg + t * ARR_BYTES + s0 * 16;
                cp16(d + r0 * 80, s + (size_t)r0 * K);
                cp16(d + (r0 + 64) * 80, s + (size_t)(r0 + 64) * K);
            }
            asm volatile("cp.async.commit_group;" ::: "memory");
            asm volatile("cp.async.wait_group 1;" ::: "memory");
        } else {
            asm volatile("cp.async.wait_group 0;" ::: "memory");
        }
        __syncthreads();

        const uint32_t stage = smb + (c & 1) * STAGE_BYTES;
        const uint32_t sAhi = stage;
        const uint32_t sAlo = stage + ARR_BYTES;
        const uint32_t sBhi = stage + 2 * ARR_BYTES;
        const uint32_t sBlo = stage + 3 * ARR_BYTES;

#pragma unroll
        for (int kb = 0; kb < 2; kb++) {
            const int kbase = kb * 16;
            uint32_t ah[2][4], al[2][4];
#pragma unroll
            for (int f = 0; f < 2; f++) {
                int mr = warp_m * 32 + f * 16 + a_mrow;
                int kc = kbase + a_kcol;
                ldsm_x4(ah[f], sAhi + mr * 80 + kc * 2);
                if (pA) ldsm_x4(al[f], sAlo + mr * 80 + kc * 2);
            }
#pragma unroll
            for (int jj = 0; jj < 4; jj++) {
                uint32_t boff = (uint32_t)(warp_n * 64 + jj * 16 + bx_row) * 80
                                + (kbase + bx_k) * 2;
                uint32_t bh4[4], bl4[4];
                ldsm_x4(bh4, sBhi + boff);
                if (pB) ldsm_x4(bl4, sBlo + boff);
#pragma unroll
                for (int f = 0; f < 2; f++) {
                    mma16816(acc[f][2 * jj],     ah[f], bh4);
                    mma16816(acc[f][2 * jj + 1], ah[f], bh4 + 2);
                    if (pB) {
                        mma16816(acc[f][2 * jj],     ah[f], bl4);
                        mma16816(acc[f][2 * jj + 1], ah[f], bl4 + 2);
                    }
                    if (pA) {
                        mma16816(acc[f][2 * jj],     al[f], bh4);
                        mma16816(acc[f][2 * jj + 1], al[f], bh4 + 2);
                    }
                }
            }
        }
        __syncthreads();
    }

    const int erow = rowBase + warp_m * 32 + (lane >> 2);
    const int ecol0 = colBase + warp_n * 64 + (lane & 3) * 2;
#pragma unroll
    for (int f = 0; f < 2; f++) {
#pragma unroll
        for (int j = 0; j < 8; j++) {
            int col = ecol0 + j * 8;
            float bx = bias[col], by = bias[col + 1];
            float v0 = acc[f][j][0] + bx, v1 = acc[f][j][1] + by;
            float v2 = acc[f][j][2] + bx, v3 = acc[f][j][3] + by;
            if (relu) {
                v0 = fmaxf(v0, 0.f); v1 = fmaxf(v1, 0.f);
                v2 = fmaxf(v2, 0.f); v3 = fmaxf(v3, 0.f);
            }
            int row = erow + f * 16;
            if (C) {
                *(float2*)(C + (size_t)row * N + col)       = make_float2(v0, v1);
                *(float2*)(C + (size_t)(row + 8) * N + col) = make_float2(v2, v3);
            }
            if (Chi) {
                if (Clo) {
                    uint32_t hp, lp;
                    split2(v0, v1, hp, lp);
                    *(uint32_t*)(Chi + (size_t)row * N + col) = hp;
                    *(uint32_t*)(Clo + (size_t)row * N + col) = lp;
                    split2(v2, v3, hp, lp);
                    *(uint32_t*)(Chi + (size_t)(row + 8) * N + col) = hp;
                    *(uint32_t*)(Clo + (size_t)(row + 8) * N + col) = lp;
                } else {
                    *(uint32_t*)(Chi + (size_t)row * N + col) = packbf(v0, v1);
                    *(uint32_t*)(Chi + (size_t)(row + 8) * N + col) = packbf(v2, v3);
                }
            }
        }
    }
}

// ====== HMMA GEMM (N=256) with fused residual-add + LayerNorm epilogue ======
// Tile 64x256 (full LN row in one CTA). 8 warps = 2m x 4n, warp tile 32x64.
// out = LN(hres + A@B^T + bias) * gamma + beta; writes fp32 out and optional
// bf16 hi/lo split. prods as in hgemm_kernel.
#define LN_N 256
#define LA_BYTES (64 * 80)        // 5120 per A array
#define LB_BYTES (256 * 80)       // 20480 per B array
#define LSTAGE (2 * LA_BYTES + 2 * LB_BYTES)   // 51200
#define LNS_OFF (2 * LSTAGE)                    // 102400
#define HGLN_SMEM (LNS_OFF + 2048)

__global__ __launch_bounds__(256, 2) void hgemm_ln_kernel(
    const uint16_t* __restrict__ Ahi, const uint16_t* __restrict__ Alo,
    const uint16_t* __restrict__ Bhi, const uint16_t* __restrict__ Blo,
    const float* __restrict__ bias, const float* __restrict__ hres,
    const float* __restrict__ gam, const float* __restrict__ bet,
    float* __restrict__ outF, uint16_t* __restrict__ Chi,
    uint16_t* __restrict__ Clo, int K, int prods)
{
    extern __shared__ char smem[];
    const uint32_t smb = smem_to_u32(smem);
    const int tid = threadIdx.x, wid = tid >> 5, lane = tid & 31;
    const int warp_m = wid & 1, warp_n = wid >> 1;
    const int rowBase = blockIdx.x * 64;
    const bool pA = (prods >= 3), pB = (prods >= 2);

    const uint16_t* Asrc[2] = { Ahi + (size_t)rowBase * K,
                                Alo ? Alo + (size_t)rowBase * K : Ahi };
    const uint16_t* Bsrc[2] = { Bhi, Blo };

    const int ar = tid >> 2, as = (tid & 3);   // A: 256 segs

    float acc[2][8][4];
#pragma unroll
    for (int f = 0; f < 2; f++)
#pragma unroll
        for (int j = 0; j < 8; j++)
#pragma unroll
            for (int e = 0; e < 4; e++) acc[f][j][e] = 0.f;

    const int nchunks = K >> 5;

    // prologue load chunk 0
    {
#pragma unroll
        for (int t = 0; t < 2; t++) {
            if (t == 1 && !pA) continue;
            cp16(smb + t * LA_BYTES + ar * 80 + as * 16,
                 Asrc[t] + (size_t)ar * K + as * 8);
        }
#pragma unroll
        for (int t = 0; t < 2; t++) {
            if (t == 1 && !pB) continue;
            uint32_t base = smb + 2 * LA_BYTES + t * LB_BYTES;
#pragma unroll
            for (int q = 0; q < 4; q++) {
                int idx = tid + q * 256;
                int br = idx >> 2, bs = idx & 3;
                cp16(base + br * 80 + bs * 16,
                     Bsrc[t] + (size_t)br * K + bs * 8);
            }
        }
    }
    asm volatile("cp.async.commit_group;" ::: "memory");

    const int a_mrow = (lane & 7) + ((lane >> 3) & 1) * 8;
    const int a_kcol = ((lane >> 4) & 1) * 8;
    const int bx_row = (lane & 7) + ((lane >> 4) & 1) * 8;
    const int bx_k   = ((lane >> 3) & 1) * 8;

    for (int c = 0; c < nchunks; c++) {
        if (c + 1 < nchunks) {
            const int co = (c + 1) * 32;
            const uint32_t stg = smb + ((c + 1) & 1) * LSTAGE;
#pragma unroll
            for (int t = 0; t < 2; t++) {
                if (t == 1 && !pA) continue;
                cp16(stg + t * LA_BYTES + ar * 80 + as * 16,
                     Asrc[t] + (size_t)ar * K + co + as * 8);
            }
#pragma unroll
            for (int t = 0; t < 2; t++) {
                if (t == 1 && !pB) continue;
                uint32_t base = stg + 2 * LA_BYTES + t * LB_BYTES;
#pragma unroll
                for (int q = 0; q < 4; q++) {
                    int idx = tid + q * 256;
                    int br = idx >> 2, bs = idx & 3;
                    cp16(base + br * 80 + bs * 16,
                         Bsrc[t] + (size_t)br * K + co + bs * 8);
                }
            }
            asm volatile("cp.async.commit_group;" ::: "memory");
            asm volatile("cp.async.wait_group 1;" ::: "memory");
        } else {
            asm volatile("cp.async.wait_group 0;" ::: "memory");
        }
        __syncthreads();

        const uint32_t stage = smb + (c & 1) * LSTAGE;
        const uint32_t sAhi = stage;
        const uint32_t sAlo = stage + LA_BYTES;
        const uint32_t sBhi = stage + 2 * LA_BYTES;
        const uint32_t sBlo = sBhi + LB_BYTES;

#pragma unroll
        for (int kb = 0; kb < 2; kb++) {
            const int kbase = kb * 16;
            uint32_t ah[2][4], al[2][4];
#pragma unroll
            for (int f = 0; f < 2; f++) {
                int mr = warp_m * 32 + f * 16 + a_mrow;
                int kc = kbase + a_kcol;
                ldsm_x4(ah[f], sAhi + mr * 80 + kc * 2);
                if (pA) ldsm_x4(al[f], sAlo + mr * 80 + kc * 2);
            }
#pragma unroll
            for (int jj = 0; jj < 4; jj++) {
                uint32_t boff = (uint32_t)(warp_n * 64 + jj * 16 + bx_row) * 80
                                + (kbase + bx_k) * 2;
                uint32_t bh4[4], bl4[4];
                ldsm_x4(bh4, sBhi + boff);
                if (pB) ldsm_x4(bl4, sBlo + boff);
#pragma unroll
                for (int f = 0; f < 2; f++) {
                    mma16816(acc[f][2 * jj],     ah[f], bh4);
                    mma16816(acc[f][2 * jj + 1], ah[f], bh4 + 2);
                    if (pB) {
                        mma16816(acc[f][2 * jj],     ah[f], bl4);
                        mma16816(acc[f][2 * jj + 1], ah[f], bl4 + 2);
                    }
                    if (pA) {
                        mma16816(acc[f][2 * jj],     al[f], bh4);
                        mma16816(acc[f][2 * jj + 1], al[f], bh4 + 2);
                    }
                }
            }
        }
        __syncthreads();
    }

    // ---- fused residual + LN epilogue ----
    float* lnS = (float*)(smem + LNS_OFF);          // [64][4]
    float* lnQ = lnS + 256;                          // [64][4]
    const int g = lane >> 2, t4 = lane & 3;
    const int ecol0 = warp_n * 64 + t4 * 2;

#pragma unroll
    for (int f = 0; f < 2; f++) {
#pragma unroll
        for (int h2 = 0; h2 < 1 + 1; h2++) {
            int lr = warp_m * 32 + g + f * 16 + h2 * 8;
            size_t rowoff = (size_t)(rowBase + lr) * LN_N;
            float psum = 0.f, psq = 0.f;
#pragma unroll
            for (int j = 0; j < 8; j++) {
                int col = ecol0 + j * 8;
                float2 hv = *(const float2*)(hres + rowoff + col);
                float v0 = acc[f][j][2 * h2]     + bias[col]     + hv.x;
                float v1 = acc[f][j][2 * h2 + 1] + bias[col + 1] + hv.y;
                acc[f][j][2 * h2] = v0;
                acc[f][j][2 * h2 + 1] = v1;
                psum += v0 + v1;
                psq = fmaf(v0, v0, psq);
                psq = fmaf(v1, v1, psq);
            }
            psum += __shfl_xor_sync(0xffffffffu, psum, 1);
            psum += __shfl_xor_sync(0xffffffffu, psum, 2);
            psq  += __shfl_xor_sync(0xffffffffu, psq, 1);
            psq  += __shfl_xor_sync(0xffffffffu, psq, 2);
            if (t4 == 0) {
                lnS[lr * 4 + warp_n] = psum;
                lnQ[lr * 4 + warp_n] = psq;
            }
        }
    }
    __syncthreads();

#pragma unroll
    for (int f = 0; f < 2; f++) {
#pragma unroll
        for (int h2 = 0; h2 < 2; h2++) {
            int lr = warp_m * 32 + g + f * 16 + h2 * 8;
            float S = lnS[lr * 4 + 0] + lnS[lr * 4 + 1] +
                      lnS[lr * 4 + 2] + lnS[lr * 4 + 3];
            float Q = lnQ[lr * 4 + 0] + lnQ[lr * 4 + 1] +
                      lnQ[lr * 4 + 2] + lnQ[lr * 4 + 3];
            float mu = S * (1.f / 256.f);
            float var = Q * (1.f / 256.f) - mu * mu;
            float rstd = rsqrtf(var + 1e-5f);
            size_t rowoff = (size_t)(rowBase + lr) * LN_N;
#pragma unroll
            for (int j = 0; j < 8; j++) {
                int col = ecol0 + j * 8;
                float y0 = (acc[f][j][2 * h2] - mu) * rstd * gam[col]
                           + bet[col];
                float y1 = (acc[f][j][2 * h2 + 1] - mu) * rstd * gam[col + 1]
                           + bet[col + 1];
                *(float2*)(outF + rowoff + col) = make_float2(y0, y1);
                if (Chi) {
                    uint32_t hp, lp;
                    split2(y0, y1, hp, lp);
                    *(uint32_t*)(Chi + rowoff + col) = hp;
                    *(uint32_t*)(Clo + rowoff + col) = lp;
                }
            }
        }
    }
}

// ------------- fused weight transpose+split kernels -------------------------
__device__ __forceinline__ void wsplit_tile(
    const float* __restrict__ W, uint16_t* __restrict__ Thi,
    uint16_t* __restrict__ Tlo, int K, int N, int k0, int n0)
{
    __shared__ float ts[32][33];
    int tx = threadIdx.x & 31, ty = threadIdx.x >> 5;
    for (int r = ty; r < 32; r += 8)
        ts[r][tx] = W[(size_t)(k0 + r) * N + n0 + tx];
    __syncthreads();
    for (int r = ty; r < 32; r += 8) {
        float v = ts[tx][r];
        __nv_bfloat16 hb = __float2bfloat16(v);
        __nv_bfloat16 lb = __float2bfloat16(v - __bfloat162float(hb));
        size_t o = (size_t)(n0 + r) * K + k0 + tx;
        Thi[o] = __bfloat16_as_ushort(hb);
        Tlo[o] = __bfloat16_as_ushort(lb);
    }
}

__global__ __launch_bounds__(256) void wsplit4_kernel(
    const float* __restrict__ Wq, const float* __restrict__ Wk,
    const float* __restrict__ Wv, const float* __restrict__ Wo,
    uint16_t* __restrict__ whi, uint16_t* __restrict__ wlo)
{
    int z = blockIdx.z, l = z >> 2, m = z & 3;
    const float* W = (m == 0 ? Wq : m == 1 ? Wk : m == 2 ? Wv : Wo)
                     + (size_t)l * 65536;
    size_t off = (size_t)l * WPL + (size_t)m * 65536;
    wsplit_tile(W, whi + off, wlo + off, 256, 256,
                blockIdx.x * 32, blockIdx.y * 32);
}
__global__ __launch_bounds__(256) void wsplitW1_kernel(
    const float* __restrict__ W1, uint16_t* __restrict__ whi,
    uint16_t* __restrict__ wlo)
{
    int l = blockIdx.z;
    size_t off = (size_t)l * WPL + 262144;
    wsplit_tile(W1 + (size_t)l * 262144, whi + off, wlo + off, 256, 1024,
                blockIdx.x * 32, blockIdx.y * 32);
}
__global__ __launch_bounds__(256) void wsplitW2_kernel(
    const float* __restrict__ W2, uint16_t* __restrict__ whi,
    uint16_t* __restrict__ wlo)
{
    int l = blockIdx.z;
    size_t off = (size_t)l * WPL + 524288;
    wsplit_tile(W2 + (size_t)l * 262144, whi + off, wlo + off, 1024, 256,
                blockIdx.x * 32, blockIdx.y * 32);
}

// ------------- pack qkv bias: [3][768] --------------------------------------
__global__ void bpack_kernel(const float* __restrict__ bq,
                             const float* __restrict__ bk,
                             const float* __restrict__ bv,
                             float* __restrict__ dst)
{
    int l = blockIdx.x, i = threadIdx.x;
    float v = (i < 256) ? bq[l * 256 + i]
            : (i < 512) ? bk[l * 256 + i - 256]
                        : bv[l * 256 + i - 512];
    dst[l * QKVN + i] = v;
}

// ---------------- input projection + split ----------------------------------
__global__ __launch_bounds__(256) void inproj_kernel(
    const float* __restrict__ x, const float* __restrict__ Win,
    const float* __restrict__ bin, float* __restrict__ h,
    uint16_t* __restrict__ hi, uint16_t* __restrict__ lo)
{
    int t = blockIdx.x;
    int d = threadIdx.x;
    __shared__ float xs[5];
    if (d < 5) xs[d] = x[t * 5 + d];
    __syncthreads();
    float acc = bin[d];
#pragma unroll
    for (int f = 0; f < 5; f++) acc = fmaf(xs[f], Win[f * DMODEL + d], acc);
    size_t o = (size_t)t * DMODEL + d;
    h[o] = acc;
    __nv_bfloat16 hb = __float2bfloat16(acc);
    __nv_bfloat16 lb = __float2bfloat16(acc - __bfloat162float(hb));
    hi[o] = __bfloat16_as_ushort(hb);
    lo[o] = __bfloat16_as_ushort(lb);
}

// ============== HMMA flash attention (single-bf16): CTA per (b, head) =======
#define AK    0
#define AV    40960
#define AQ    74240
#define AMADD 94720
#define ATTN_SMEM (AMADD + 2048)

__global__ __launch_bounds__(512, 2) void attn_kernel(
    const uint16_t* __restrict__ qkvh, const int* __restrict__ mask,
    uint16_t* __restrict__ Ohi)
{
    extern __shared__ char sm[];
    const int b  = blockIdx.x >> 3;
    const int hh = blockIdx.x & 7;
    const int tid = threadIdx.x;
    const int warp = tid >> 5, lane = tid & 31;
    const size_t qOff = (size_t)b * SEQ * QKVN + hh * HDIM;
    const size_t oOff = (size_t)b * SEQ * DMODEL + hh * HDIM;
    const float scale = 0.17677669529663687f;

    uint16_t* Ks = (uint16_t*)(sm + AK);
    uint16_t* Vs = (uint16_t*)(sm + AV);
    uint16_t* Qs = (uint16_t*)(sm + AQ);
    float*  Madd = (float*)(sm + AMADD);

    for (int idx = tid; idx < SEQ * 8; idx += 512) {
        int j = idx >> 3, d4 = (idx & 7) * 4;
        uint2 kw = *(const uint2*)(qkvh + qOff + (size_t)j * QKVN + 256 + d4);
        *(uint2*)(Ks + j * 40 + d4) = kw;
        uint2 vw = *(const uint2*)(qkvh + qOff + (size_t)j * QKVN + 512 + d4);
        uint16_t vv[4];
        *(uint2*)vv = vw;
        Vs[(d4 + 0) * 520 + j] = vv[0];
        Vs[(d4 + 1) * 520 + j] = vv[1];
        Vs[(d4 + 2) * 520 + j] = vv[2];
        Vs[(d4 + 3) * 520 + j] = vv[3];
    }
    for (int j = tid; j < SEQ; j += 512)
        Madd[j] = mask[b * SEQ + j] ? -INFINITY : 0.f;
    __syncthreads();

    const uint32_t smb = smem_to_u32(sm);
    const int a_row = (lane & 7) + ((lane >> 3) & 1) * 8;
    const int a_col = ((lane >> 4) & 1) * 8;
    const int bx_row = (lane & 7) + ((lane >> 4) & 1) * 8;
    const int bx_k   = ((lane >> 3) & 1) * 8;
    const int g = lane >> 2, t4 = lane & 3;

    for (int pass = 0; pass < 2; pass++) {
        const int row0 = warp * 32 + pass * 16;

        for (int e = lane; e < 16 * 8; e += 32) {
            int r = e >> 3, d4 = (e & 7) * 4;
            uint2 qw = *(const uint2*)(qkvh + qOff +
                                       (size_t)(row0 + r) * QKVN + d4);
            *(uint2*)(Qs + warp * 640 + r * 40 + d4) = qw;
        }
        __syncwarp();

        uint32_t ah[2][4];
#pragma unroll
        for (int kb = 0; kb < 2; kb++) {
            uint32_t off = warp * 1280 + a_row * 80 + (kb * 16 + a_col) * 2;
            ldsm_x4(ah[kb], smb + AQ + off);
        }
        __syncwarp();

        float m0 = -1e30f, m1 = -1e30f, l0 = 0.f, l1 = 0.f;
        float o[4][4];
#pragma unroll
        for (int dt = 0; dt < 4; dt++)
#pragma unroll
            for (int e = 0; e < 4; e++) o[dt][e] = 0.f;

        for (int jc = 0; jc < 8; jc++) {
            float s[8][4];
#pragma unroll
            for (int jt = 0; jt < 8; jt++)
#pragma unroll
                for (int e = 0; e < 4; e++) s[jt][e] = 0.f;

#pragma unroll
            for (int jp = 0; jp < 4; jp++) {
                uint32_t roff = (uint32_t)(jc * 64 + jp * 16 + bx_row) * 80;
#pragma unroll
                for (int kb = 0; kb < 2; kb++) {
                    uint32_t bh4[4];
                    ldsm_x4(bh4, smb + AK + roff + (kb * 16 + bx_k) * 2);
                    mma16816(s[2 * jp],     ah[kb], bh4);
                    mma16816(s[2 * jp + 1], ah[kb], bh4 + 2);
                }
            }

            float cm0 = -1e30f, cm1 = -1e30f;
#pragma unroll
            for (int jt = 0; jt < 8; jt++) {
                int col = jc * 64 + jt * 8 + t4 * 2;
                float ma = Madd[col], mb = Madd[col + 1];
                s[jt][0] = fmaf(s[jt][0], scale, ma);
                s[jt][1] = fmaf(s[jt][1], scale, mb);
                s[jt][2] = fmaf(s[jt][2], scale, ma);
                s[jt][3] = fmaf(s[jt][3], scale, mb);
                cm0 = fmaxf(cm0, fmaxf(s[jt][0], s[jt][1]));
                cm1 = fmaxf(cm1, fmaxf(s[jt][2], s[jt][3]));
            }
            cm0 = fmaxf(cm0, __shfl_xor_sync(0xffffffffu, cm0, 1));
            cm0 = fmaxf(cm0, __shfl_xor_sync(0xffffffffu, cm0, 2));
            cm1 = fmaxf(cm1, __shfl_xor_sync(0xffffffffu, cm1, 1));
            cm1 = fmaxf(cm1, __shfl_xor_sync(0xffffffffu, cm1, 2));

            float mn0 = fmaxf(m0, cm0), mn1 = fmaxf(m1, cm1);
            float sc0 = __expf(m0 - mn0), sc1 = __expf(m1 - mn1);
            m0 = mn0; m1 = mn1;

            float sum0 = 0.f, sum1 = 0.f;
#pragma unroll
            for (int jt = 0; jt < 8; jt++) {
                s[jt][0] = __expf(s[jt][0] - m0);
                s[jt][1] = __expf(s[jt][1] - m0);
                s[jt][2] = __expf(s[jt][2] - m1);
                s[jt][3] = __expf(s[jt][3] - m1);
                sum0 += s[jt][0] + s[jt][1];
                sum1 += s[jt][2] + s[jt][3];
            }
            sum0 += __shfl_xor_sync(0xffffffffu, sum0, 1);
            sum0 += __shfl_xor_sync(0xffffffffu, sum0, 2);
            sum1 += __shfl_xor_sync(0xffffffffu, sum1, 1);
            sum1 += __shfl_xor_sync(0xffffffffu, sum1, 2);
            l0 = l0 * sc0 + sum0;
            l1 = l1 * sc1 + sum1;
#pragma unroll
            for (int dt = 0; dt < 4; dt++) {
                o[dt][0] *= sc0; o[dt][1] *= sc0;
                o[dt][2] *= sc1; o[dt][3] *= sc1;
            }

#pragma unroll
            for (int kk = 0; kk < 4; kk++) {
                uint32_t pa[4];
                pa[0] = packbf(s[2 * kk][0],     s[2 * kk][1]);
                pa[1] = packbf(s[2 * kk][2],     s[2 * kk][3]);
                pa[2] = packbf(s[2 * kk + 1][0], s[2 * kk + 1][1]);
                pa[3] = packbf(s[2 * kk + 1][2], s[2 * kk + 1][3]);
                uint32_t jb = (uint32_t)(jc * 64 + kk * 16 + bx_k);
#pragma unroll
                for (int dp = 0; dp < 2; dp++) {
                    uint32_t bh4[4];
                    ldsm_x4(bh4, smb + AV +
                            (uint32_t)(dp * 16 + bx_row) * 1040 + jb * 2);
                    mma16816(o[2 * dp],     pa, bh4);
                    mma16816(o[2 * dp + 1], pa, bh4 + 2);
                }
            }
        }

        float i0 = (l0 > 0.f) ? (1.f / l0) : 0.f;
        float i1 = (l1 > 0.f) ? (1.f / l1) : 0.f;
        const int rg = row0 + g;
#pragma unroll
        for (int dt = 0; dt < 4; dt++) {
            int col = dt * 8 + t4 * 2;
            *(uint32_t*)(Ohi + oOff + (size_t)rg * DMODEL + col) =
                packbf(o[dt][0] * i0, o[dt][1] * i0);
            *(uint32_t*)(Ohi + oOff + (size_t)(rg + 8) * DMODEL + col) =
                packbf(o[dt][2] * i1, o[dt][3] * i1);
        }
        __syncwarp();
    }
}

// ---------------- launch ----------------------------------------------------
extern "C" void kernel_launch(void* const* d_in, const int* in_sizes, int n_in,
                              void* d_out, int out_size)
{
    const float* x    = (const float*)d_in[0];
    const int*   mask = (const int*)d_in[1];
    const float* Win = (const float*)d_in[2];
    const float* bin = (const float*)d_in[3];
    const float* Wq  = (const float*)d_in[4];
    const float* bq  = (const float*)d_in[5];
    const float* Wk  = (const float*)d_in[6];
    const float* bk  = (const float*)d_in[7];
    const float* Wv  = (const float*)d_in[8];
    const float* bv  = (const float*)d_in[9];
    const float* Wo  = (const float*)d_in[10];
    const float* bo  = (const float*)d_in[11];
    const float* g1  = (const float*)d_in[12];
    const float* b1  = (const float*)d_in[13];
    const float* W1  = (const float*)d_in[14];
    const float* c1  = (const float*)d_in[15];
    const float* W2  = (const float*)d_in[16];
    const float* c2  = (const float*)d_in[17];
    const float* g2  = (const float*)d_in[18];
    const float* b2  = (const float*)d_in[19];
    float* out = (float*)d_out;

    float *h, *bqkv;
    uint16_t *qkvh, *ahi, *alo, *bhi, *blo, *whi, *wlo;
    cudaGetSymbolAddress((void**)&h,    g_h);
    cudaGetSymbolAddress((void**)&qkvh, g_qkvh);
    cudaGetSymbolAddress((void**)&bqkv, g_bqkv);
    cudaGetSymbolAddress((void**)&ahi,  g_ahi);
    cudaGetSymbolAddress((void**)&alo,  g_alo);
    cudaGetSymbolAddress((void**)&bhi,  g_bhi);
    cudaGetSymbolAddress((void**)&blo,  g_blo);
    cudaGetSymbolAddress((void**)&whi,  g_whi);
    cudaGetSymbolAddress((void**)&wlo,  g_wlo);

    cudaFuncSetAttribute(attn_kernel,
                         cudaFuncAttributeMaxDynamicSharedMemorySize,
                         ATTN_SMEM);
    cudaFuncSetAttribute(hgemm_kernel,
                         cudaFuncAttributeMaxDynamicSharedMemorySize,
                         HG_SMEM);
    cudaFuncSetAttribute(hgemm_ln_kernel,
                         cudaFuncAttributeMaxDynamicSharedMemorySize,
                         HGLN_SMEM);

    // ---- prep ----
    wsplit4_kernel<<<dim3(8, 8, 12), 256>>>(Wq, Wk, Wv, Wo, whi, wlo);
    wsplitW1_kernel<<<dim3(8, 32, 3), 256>>>(W1, whi, wlo);
    wsplitW2_kernel<<<dim3(32, 8, 3), 256>>>(W2, whi, wlo);
    bpack_kernel<<<NLAYER, QKVN>>>(bq, bk, bv, bqkv);

    inproj_kernel<<<MTOK, 256>>>(x, Win, bin, h, ahi, alo);

    dim3 gQKV(QKVN / 128, 128);
    dim3 gF(8, 128);
    const int gLN = MTOK / 64;   // 256 CTAs

    for (int l = 0; l < NLAYER; l++) {
        size_t wo = (size_t)l * WPL;

        // fused QKV projection (hi*hi only), bf16-packed output
        hgemm_kernel<<<gQKV, 256, HG_SMEM>>>(ahi, nullptr,
            whi + wo, wlo + wo, bqkv + l * QKVN,
            nullptr, qkvh, nullptr, MTOK, QKVN, DMODEL, 0, 1);

        // attention -> packed bf16 output into ahi (A of Wo)
        attn_kernel<<<32 * NHEAD, 512, ATTN_SMEM>>>(qkvh, mask, ahi);

        // Wo + residual + LN1 fused: h = LN(h + attn@Wo + bo); split to ahi/alo
        hgemm_ln_kernel<<<gLN, 256, HGLN_SMEM>>>(ahi, nullptr,
            whi + wo + 196608, wlo + wo + 196608, bo + l * DMODEL,
            h, g1 + l * DMODEL, b1 + l * DMODEL,
            h, ahi, alo, DMODEL, 2);

        // FFN W1 (prods=3, relu, split out)
        hgemm_kernel<<<gF, 256, HG_SMEM>>>(ahi, alo,
            whi + wo + 262144, wlo + wo + 262144, c1 + l * FFDIM,
            nullptr, bhi, blo, MTOK, FFDIM, DMODEL, 1, 3);

        // W2 + residual + LN2 fused
        float* dst = (l == NLAYER - 1) ? out : h;
        uint16_t* nhi = (l == NLAYER - 1) ? nullptr : ahi;
        uint16_t* nlo = (l == NLAYER - 1) ? nullptr : alo;
        hgemm_ln_kernel<<<gLN, 256, HGLN_SMEM>>>(bhi, blo,
            whi + wo + 524288, wlo + wo + 524288, c2 + l * DMODEL,
            h, g2 + l * DMODEL, b2 + l * DMODEL,
            dst, nhi, nlo, FFDIM, 3);
    }
}

// round 17
// speedup vs baseline: 1.0317x; 1.0317x over previous
#include <cuda_runtime.h>
#include <cuda_bf16.h>
#include <math.h>
#include <stdint.h>

#define MTOK 16384
#define DMODEL 256
#define FFDIM 1024
#define NHEAD 8
#define HDIM 32
#define SEQ 512
#define NLAYER 3
#define QKVN 768

// ---------------- scratch (device globals; no allocation allowed) ------------
__device__ float g_h  [MTOK * DMODEL];
__device__ float g_r  [MTOK * DMODEL];
__device__ float g_r2 [MTOK * DMODEL];
__device__ uint16_t g_qkvh[MTOK * QKVN];
__device__ uint16_t g_ahi[MTOK * DMODEL];
__device__ uint16_t g_alo[MTOK * DMODEL];
__device__ uint16_t g_bhi[MTOK * FFDIM];
__device__ uint16_t g_blo[MTOK * FFDIM];
#define WPL 786432
__device__ uint16_t g_whi[3 * WPL];
__device__ uint16_t g_wlo[3 * WPL];
__device__ float g_bqkv[3 * QKVN];

__device__ __forceinline__ uint32_t smem_to_u32(const void* p) {
    uint32_t a;
    asm("{ .reg .u64 t; cvta.to.shared.u64 t, %1; cvt.u32.u64 %0, t; }"
        : "=r"(a) : "l"(p));
    return a;
}
__device__ __forceinline__ void ldsm_x4(uint32_t* r, uint32_t addr) {
    asm volatile("ldmatrix.sync.aligned.m8n8.x4.shared.b16 {%0,%1,%2,%3}, [%4];"
                 : "=r"(r[0]), "=r"(r[1]), "=r"(r[2]), "=r"(r[3]) : "r"(addr));
}
__device__ __forceinline__ void mma16816(float* c, const uint32_t* a,
                                         const uint32_t* b) {
    asm volatile(
        "mma.sync.aligned.m16n8k16.row.col.f32.bf16.bf16.f32 "
        "{%0,%1,%2,%3}, {%4,%5,%6,%7}, {%8,%9}, {%0,%1,%2,%3};"
        : "+f"(c[0]), "+f"(c[1]), "+f"(c[2]), "+f"(c[3])
        : "r"(a[0]), "r"(a[1]), "r"(a[2]), "r"(a[3]), "r"(b[0]), "r"(b[1]));
}
__device__ __forceinline__ uint32_t packbf(float lo, float hi) {
    uint32_t r;
    asm("cvt.rn.bf16x2.f32 %0, %1, %2;" : "=r"(r) : "f"(hi), "f"(lo));
    return r;
}
__device__ __forceinline__ void split2(float a, float b,
                                       uint32_t& hi, uint32_t& lo) {
    __nv_bfloat16 ha = __float2bfloat16(a);
    __nv_bfloat16 hb = __float2bfloat16(b);
    float ra = a - __bfloat162float(ha);
    float rb = b - __bfloat162float(hb);
    hi = (uint32_t)__bfloat16_as_ushort(ha) |
         ((uint32_t)__bfloat16_as_ushort(hb) << 16);
    __nv_bfloat16 la = __float2bfloat16(ra);
    __nv_bfloat16 lb = __float2bfloat16(rb);
    lo = (uint32_t)__bfloat16_as_ushort(la) |
         ((uint32_t)__bfloat16_as_ushort(lb) << 16);
}
__device__ __forceinline__ void cp16(uint32_t saddr, const void* g) {
    asm volatile("cp.async.cg.shared.global [%0], [%1], 16;"
                 :: "r"(saddr), "l"(g));
}

// ================= HMMA GEMM: C = A@B^T + bias (opt relu) ===================
// prods=1: ah*bh. prods=2: ah*bh + ah*bl. prods=3: + al*bh (fp32 emulation).
#define STRIDE_E 40
#define ARR_BYTES (128 * STRIDE_E * 2)
#define STAGE_BYTES (4 * ARR_BYTES)
#define HG_SMEM (2 * STAGE_BYTES)

__global__ __launch_bounds__(256, 2) void hgemm_kernel(
    const uint16_t* __restrict__ Ahi, const uint16_t* __restrict__ Alo,
    const uint16_t* __restrict__ Bhi, const uint16_t* __restrict__ Blo,
    const float* __restrict__ bias, float* __restrict__ C,
    uint16_t* __restrict__ Chi, uint16_t* __restrict__ Clo,
    int M, int N, int K, int relu, int prods)
{
    extern __shared__ char smem[];
    const uint32_t smb = smem_to_u32(smem);
    const int tid = threadIdx.x, wid = tid >> 5, lane = tid & 31;
    const int warp_m = wid & 3, warp_n = wid >> 2;
    const int rowBase = blockIdx.y * 128, colBase = blockIdx.x * 128;
    const bool pA = (prods >= 3), pB = (prods >= 2);

    const uint16_t* srcs[4] = {
        Ahi + (size_t)rowBase * K, Alo + (size_t)rowBase * K,
        Bhi + (size_t)colBase * K, Blo + (size_t)colBase * K };

    const int r0 = tid >> 2, s0 = (tid & 3);

    float acc[2][8][4];
#pragma unroll
    for (int f = 0; f < 2; f++)
#pragma unroll
        for (int j = 0; j < 8; j++)
#pragma unroll
            for (int e = 0; e < 4; e++) acc[f][j][e] = 0.f;

    const int nchunks = K >> 5;

    {
#pragma unroll
        for (int t = 0; t < 4; t++) {
            if (t == 1 && !pA) continue;
            if (t == 3 && !pB) continue;
            const uint16_t* s = srcs[t] + s0 * 8;
            uint32_t d = smb + t * ARR_BYTES + s0 * 16;
            cp16(d + r0 * 80, s + (size_t)r0 * K);
            cp16(d + (r0 + 64) * 80, s + (size_t)(r0 + 64) * K);
        }
    }
    asm volatile("cp.async.commit_group;" ::: "memory");

    const int a_mrow = (lane & 7) + ((lane >> 3) & 1) * 8;
    const int a_kcol = ((lane >> 4) & 1) * 8;
    const int bx_row = (lane & 7) + ((lane >> 4) & 1) * 8;
    const int bx_k   = ((lane >> 3) & 1) * 8;

    for (int c = 0; c < nchunks; c++) {
        if (c + 1 < nchunks) {
            const int co = (c + 1) * 32;
            const uint32_t stg = smb + ((c + 1) & 1) * STAGE_BYTES;
#pragma unroll
            for (int t = 0; t < 4; t++) {
                if (t == 1 && !pA) continue;
                if (t == 3 && !pB) continue;
                const uint16_t* s = srcs[t] + co + s0 * 8;
                uint32_t d = stg + t * ARR_BYTES + s0 * 16;
                cp16(d + r0 * 80, s + (size_t)r0 * K);
                cp16(d + (r0 + 64) * 80, s + (size_t)(r0 + 64) * K);
            }
            asm volatile("cp.async.commit_group;" ::: "memory");
            asm volatile("cp.async.wait_group 1;" ::: "memory");
        } else {
            asm volatile("cp.async.wait_group 0;" ::: "memory");
        }
        __syncthreads();

        const uint32_t stage = smb + (c & 1) * STAGE_BYTES;
        const uint32_t sAhi = stage;
        const uint32_t sAlo = stage + ARR_BYTES;
        const uint32_t sBhi = stage + 2 * ARR_BYTES;
        const uint32_t sBlo = stage + 3 * ARR_BYTES;

#pragma unroll
        for (int kb = 0; kb < 2; kb++) {
            const int kbase = kb * 16;
            uint32_t ah[2][4], al[2][4];
#pragma unroll
            for (int f = 0; f < 2; f++) {
                int mr = warp_m * 32 + f * 16 + a_mrow;
                int kc = kbase + a_kcol;
                ldsm_x4(ah[f], sAhi + mr * 80 + kc * 2);
                if (pA) ldsm_x4(al[f], sAlo + mr * 80 + kc * 2);
            }
#pragma unroll
            for (int jj = 0; jj < 4; jj++) {
                uint32_t boff = (uint32_t)(warp_n * 64 + jj * 16 + bx_row) * 80
                                + (kbase + bx_k) * 2;
                uint32_t bh4[4], bl4[4];
                ldsm_x4(bh4, sBhi + boff);
                if (pB) ldsm_x4(bl4, sBlo + boff);
#pragma unroll
                for (int f = 0; f < 2; f++) {
                    mma16816(acc[f][2 * jj],     ah[f], bh4);
                    mma16816(acc[f][2 * jj + 1], ah[f], bh4 + 2);
                    if (pB) {
                        mma16816(acc[f][2 * jj],     ah[f], bl4);
                        mma16816(acc[f][2 * jj + 1], ah[f], bl4 + 2);
                    }
                    if (pA) {
                        mma16816(acc[f][2 * jj],     al[f], bh4);
                        mma16816(acc[f][2 * jj + 1], al[f], bh4 + 2);
                    }
                }
            }
        }
        __syncthreads();
    }

    const int erow = rowBase + warp_m * 32 + (lane >> 2);
    const int ecol0 = colBase + warp_n * 64 + (lane & 3) * 2;
#pragma unroll
    for (int f = 0; f < 2; f++) {
#pragma unroll
        for (int j = 0; j < 8; j++) {
            int col = ecol0 + j * 8;
            float bx = bias[col], by = bias[col + 1];
            float v0 = acc[f][j][0] + bx, v1 = acc[f][j][1] + by;
            float v2 = acc[f][j][2] + bx, v3 = acc[f][j][3] + by;
            if (relu) {
                v0 = fmaxf(v0, 0.f); v1 = fmaxf(v1, 0.f);
                v2 = fmaxf(v2, 0.f); v3 = fmaxf(v3, 0.f);
            }
            int row = erow + f * 16;
            if (C) {
                *(float2*)(C + (size_t)row * N + col)       = make_float2(v0, v1);
                *(float2*)(C + (size_t)(row + 8) * N + col) = make_float2(v2, v3);
            }
            if (Chi) {
                if (Clo) {
                    uint32_t hp, lp;
                    split2(v0, v1, hp, lp);
                    *(uint32_t*)(Chi + (size_t)row * N + col) = hp;
                    *(uint32_t*)(Clo + (size_t)row * N + col) = lp;
                    split2(v2, v3, hp, lp);
                    *(uint32_t*)(Chi + (size_t)(row + 8) * N + col) = hp;
                    *(uint32_t*)(Clo + (size_t)(row + 8) * N + col) = lp;
                } else {
                    *(uint32_t*)(Chi + (size_t)row * N + col) = packbf(v0, v1);
                    *(uint32_t*)(Chi + (size_t)(row + 8) * N + col) = packbf(v2, v3);
                }
            }
        }
    }
}

// ------------- single-launch weight transpose+split (all matrices) ----------
__device__ __forceinline__ void wsplit_tile(
    const float* __restrict__ W, uint16_t* __restrict__ Thi,
    uint16_t* __restrict__ Tlo, int K, int N, int k0, int n0)
{
    __shared__ float ts[32][33];
    int tx = threadIdx.x & 31, ty = threadIdx.x >> 5;
    for (int r = ty; r < 32; r += 8)
        ts[r][tx] = W[(size_t)(k0 + r) * N + n0 + tx];
    __syncthreads();
    for (int r = ty; r < 32; r += 8) {
        float v = ts[tx][r];
        __nv_bfloat16 hb = __float2bfloat16(v);
        __nv_bfloat16 lb = __float2bfloat16(v - __bfloat162float(hb));
        size_t o = (size_t)(n0 + r) * K + k0 + tx;
        Thi[o] = __bfloat16_as_ushort(hb);
        Tlo[o] = __bfloat16_as_ushort(lb);
    }
}

// flat grid of 2304 tile-blocks:
//  [0,768):    QKVO  (12 mats of 256x256, 64 tiles each)
//  [768,1536): W1    (3 mats of 256x1024, 256 tiles each)
//  [1536,2304):W2    (3 mats of 1024x256, 256 tiles each)
__global__ __launch_bounds__(256) void wsplit_all_kernel(
    const float* __restrict__ Wq, const float* __restrict__ Wk,
    const float* __restrict__ Wv, const float* __restrict__ Wo,
    const float* __restrict__ W1, const float* __restrict__ W2,
    uint16_t* __restrict__ whi, uint16_t* __restrict__ wlo)
{
    int idx = blockIdx.x;
    if (idx < 768) {
        int z = idx >> 6, t = idx & 63;
        int l = z >> 2, m = z & 3;
        const float* W = (m == 0 ? Wq : m == 1 ? Wk : m == 2 ? Wv : Wo)
                         + (size_t)l * 65536;
        size_t off = (size_t)l * WPL + (size_t)m * 65536;
        wsplit_tile(W, whi + off, wlo + off, 256, 256,
                    (t & 7) * 32, (t >> 3) * 32);
    } else if (idx < 1536) {
        int r = idx - 768;
        int l = r >> 8, t = r & 255;
        size_t off = (size_t)l * WPL + 262144;
        wsplit_tile(W1 + (size_t)l * 262144, whi + off, wlo + off, 256, 1024,
                    (t & 7) * 32, (t >> 3) * 32);
    } else {
        int r = idx - 1536;
        int l = r >> 8, t = r & 255;
        size_t off = (size_t)l * WPL + 524288;
        wsplit_tile(W2 + (size_t)l * 262144, whi + off, wlo + off, 1024, 256,
                    (t & 31) * 32, (t >> 5) * 32);
    }
}

// ------------- pack qkv bias: [3][768] --------------------------------------
__global__ void bpack_kernel(const float* __restrict__ bq,
                             const float* __restrict__ bk,
                             const float* __restrict__ bv,
                             float* __restrict__ dst)
{
    int l = blockIdx.x, i = threadIdx.x;
    float v = (i < 256) ? bq[l * 256 + i]
            : (i < 512) ? bk[l * 256 + i - 256]
                        : bv[l * 256 + i - 512];
    dst[l * QKVN + i] = v;
}

// ---------------- input projection + split ----------------------------------
__global__ __launch_bounds__(256) void inproj_kernel(
    const float* __restrict__ x, const float* __restrict__ Win,
    const float* __restrict__ bin, float* __restrict__ h,
    uint16_t* __restrict__ hi, uint16_t* __restrict__ lo)
{
    int t = blockIdx.x;
    int d = threadIdx.x;
    __shared__ float xs[5];
    if (d < 5) xs[d] = x[t * 5 + d];
    __syncthreads();
    float acc = bin[d];
#pragma unroll
    for (int f = 0; f < 5; f++) acc = fmaf(xs[f], Win[f * DMODEL + d], acc);
    size_t o = (size_t)t * DMODEL + d;
    h[o] = acc;
    __nv_bfloat16 hb = __float2bfloat16(acc);
    __nv_bfloat16 lb = __float2bfloat16(acc - __bfloat162float(hb));
    hi[o] = __bfloat16_as_ushort(hb);
    lo[o] = __bfloat16_as_ushort(lb);
}

// ============== HMMA flash attention (single-bf16): CTA per (b, head) =======
// exp2-domain softmax: scale includes log2(e); exp2f replaces __expf.
#define AK    0
#define AV    40960
#define AQ    74240
#define AMADD 94720
#define ATTN_SMEM (AMADD + 2048)

__global__ __launch_bounds__(512, 2) void attn_kernel(
    const uint16_t* __restrict__ qkvh, const int* __restrict__ mask,
    uint16_t* __restrict__ Ohi)
{
    extern __shared__ char sm[];
    const int b  = blockIdx.x >> 3;
    const int hh = blockIdx.x & 7;
    const int tid = threadIdx.x;
    const int warp = tid >> 5, lane = tid & 31;
    const size_t qOff = (size_t)b * SEQ * QKVN + hh * HDIM;
    const size_t oOff = (size_t)b * SEQ * DMODEL + hh * HDIM;
    // 1/sqrt(32) * log2(e): softmax computed in exp2 domain (base change
    // cancels in the normalization).
    const float scale = 0.17677669529663687f * 1.4426950408889634f;

    uint16_t* Ks = (uint16_t*)(sm + AK);    // [512][40]
    uint16_t* Vs = (uint16_t*)(sm + AV);    // [32][520] transposed
    uint16_t* Qs = (uint16_t*)(sm + AQ);    // [16 warps][16][40]
    float*  Madd = (float*)(sm + AMADD);

    for (int idx = tid; idx < SEQ * 8; idx += 512) {
        int j = idx >> 3, d4 = (idx & 7) * 4;
        uint2 kw = *(const uint2*)(qkvh + qOff + (size_t)j * QKVN + 256 + d4);
        *(uint2*)(Ks + j * 40 + d4) = kw;
        uint2 vw = *(const uint2*)(qkvh + qOff + (size_t)j * QKVN + 512 + d4);
        uint16_t vv[4];
        *(uint2*)vv = vw;
        Vs[(d4 + 0) * 520 + j] = vv[0];
        Vs[(d4 + 1) * 520 + j] = vv[1];
        Vs[(d4 + 2) * 520 + j] = vv[2];
        Vs[(d4 + 3) * 520 + j] = vv[3];
    }
    for (int j = tid; j < SEQ; j += 512)
        Madd[j] = mask[b * SEQ + j] ? -INFINITY : 0.f;
    __syncthreads();

    const uint32_t smb = smem_to_u32(sm);
    const int a_row = (lane & 7) + ((lane >> 3) & 1) * 8;
    const int a_col = ((lane >> 4) & 1) * 8;
    const int bx_row = (lane & 7) + ((lane >> 4) & 1) * 8;
    const int bx_k   = ((lane >> 3) & 1) * 8;
    const int g = lane >> 2, t4 = lane & 3;

    for (int pass = 0; pass < 2; pass++) {
        const int row0 = warp * 32 + pass * 16;

        for (int e = lane; e < 16 * 8; e += 32) {
            int r = e >> 3, d4 = (e & 7) * 4;
            uint2 qw = *(const uint2*)(qkvh + qOff +
                                       (size_t)(row0 + r) * QKVN + d4);
            *(uint2*)(Qs + warp * 640 + r * 40 + d4) = qw;
        }
        __syncwarp();

        uint32_t ah[2][4];
#pragma unroll
        for (int kb = 0; kb < 2; kb++) {
            uint32_t off = warp * 1280 + a_row * 80 + (kb * 16 + a_col) * 2;
            ldsm_x4(ah[kb], smb + AQ + off);
        }
        __syncwarp();

        float m0 = -1e30f, m1 = -1e30f, l0 = 0.f, l1 = 0.f;
        float o[4][4];
#pragma unroll
        for (int dt = 0; dt < 4; dt++)
#pragma unroll
            for (int e = 0; e < 4; e++) o[dt][e] = 0.f;

        for (int jc = 0; jc < 8; jc++) {
            float s[8][4];
#pragma unroll
            for (int jt = 0; jt < 8; jt++)
#pragma unroll
                for (int e = 0; e < 4; e++) s[jt][e] = 0.f;

#pragma unroll
            for (int jp = 0; jp < 4; jp++) {
                uint32_t roff = (uint32_t)(jc * 64 + jp * 16 + bx_row) * 80;
#pragma unroll
                for (int kb = 0; kb < 2; kb++) {
                    uint32_t bh4[4];
                    ldsm_x4(bh4, smb + AK + roff + (kb * 16 + bx_k) * 2);
                    mma16816(s[2 * jp],     ah[kb], bh4);
                    mma16816(s[2 * jp + 1], ah[kb], bh4 + 2);
                }
            }

            float cm0 = -1e30f, cm1 = -1e30f;
#pragma unroll
            for (int jt = 0; jt < 8; jt++) {
                int col = jc * 64 + jt * 8 + t4 * 2;
                float ma = Madd[col], mb = Madd[col + 1];
                s[jt][0] = fmaf(s[jt][0], scale, ma);
                s[jt][1] = fmaf(s[jt][1], scale, mb);
                s[jt][2] = fmaf(s[jt][2], scale, ma);
                s[jt][3] = fmaf(s[jt][3], scale, mb);
                cm0 = fmaxf(cm0, fmaxf(s[jt][0], s[jt][1]));
                cm1 = fmaxf(cm1, fmaxf(s[jt][2], s[jt][3]));
            }
            cm0 = fmaxf(cm0, __shfl_xor_sync(0xffffffffu, cm0, 1));
            cm0 = fmaxf(cm0, __shfl_xor_sync(0xffffffffu, cm0, 2));
            cm1 = fmaxf(cm1, __shfl_xor_sync(0xffffffffu, cm1, 1));
            cm1 = fmaxf(cm1, __shfl_xor_sync(0xffffffffu, cm1, 2));

            float mn0 = fmaxf(m0, cm0), mn1 = fmaxf(m1, cm1);
            float sc0 = exp2f(m0 - mn0), sc1 = exp2f(m1 - mn1);
            m0 = mn0; m1 = mn1;

            float sum0 = 0.f, sum1 = 0.f;
#pragma unroll
            for (int jt = 0; jt < 8; jt++) {
                s[jt][0] = exp2f(s[jt][0] - m0);
                s[jt][1] = exp2f(s[jt][1] - m0);
                s[jt][2] = exp2f(s[jt][2] - m1);
                s[jt][3] = exp2f(s[jt][3] - m1);
                sum0 += s[jt][0] + s[jt][1];
                sum1 += s[jt][2] + s[jt][3];
            }
            sum0 += __shfl_xor_sync(0xffffffffu, sum0, 1);
            sum0 += __shfl_xor_sync(0xffffffffu, sum0, 2);
            sum1 += __shfl_xor_sync(0xffffffffu, sum1, 1);
            sum1 += __shfl_xor_sync(0xffffffffu, sum1, 2);
            l0 = l0 * sc0 + sum0;
            l1 = l1 * sc1 + sum1;
#pragma unroll
            for (int dt = 0; dt < 4; dt++) {
                o[dt][0] *= sc0; o[dt][1] *= sc0;
                o[dt][2] *= sc1; o[dt][3] *= sc1;
            }

#pragma unroll
            for (int kk = 0; kk < 4; kk++) {
                uint32_t pa[4];
                pa[0] = packbf(s[2 * kk][0],     s[2 * kk][1]);
                pa[1] = packbf(s[2 * kk][2],     s[2 * kk][3]);
                pa[2] = packbf(s[2 * kk + 1][0], s[2 * kk + 1][1]);
                pa[3] = packbf(s[2 * kk + 1][2], s[2 * kk + 1][3]);
                uint32_t jb = (uint32_t)(jc * 64 + kk * 16 + bx_k);
#pragma unroll
                for (int dp = 0; dp < 2; dp++) {
                    uint32_t bh4[4];
                    ldsm_x4(bh4, smb + AV +
                            (uint32_t)(dp * 16 + bx_row) * 1040 + jb * 2);
                    mma16816(o[2 * dp],     pa, bh4);
                    mma16816(o[2 * dp + 1], pa, bh4 + 2);
                }
            }
        }

        float i0 = (l0 > 0.f) ? (1.f / l0) : 0.f;
        float i1 = (l1 > 0.f) ? (1.f / l1) : 0.f;
        const int rg = row0 + g;
#pragma unroll
        for (int dt = 0; dt < 4; dt++) {
            int col = dt * 8 + t4 * 2;
            *(uint32_t*)(Ohi + oOff + (size_t)rg * DMODEL + col) =
                packbf(o[dt][0] * i0, o[dt][1] * i0);
            *(uint32_t*)(Ohi + oOff + (size_t)(rg + 8) * DMODEL + col) =
                packbf(o[dt][2] * i1, o[dt][3] * i1);
        }
        __syncwarp();
    }
}

// ---------- fused residual add + LayerNorm (+ optional hi/lo split) ---------
__global__ __launch_bounds__(256) void add_ln_kernel(
    const float* __restrict__ a, const float* __restrict__ r,
    const float* __restrict__ g, const float* __restrict__ bb,
    float* __restrict__ out, uint16_t* __restrict__ hi,
    uint16_t* __restrict__ lo)
{
    const int warp = threadIdx.x >> 5, lane = threadIdx.x & 31;
    const int token = blockIdx.x * 8 + warp;
    const size_t base = (size_t)token * DMODEL + lane * 8;

    float4 xa = *(const float4*)(a + base);
    float4 xb = *(const float4*)(a + base + 4);
    float4 ra = *(const float4*)(r + base);
    float4 rb = *(const float4*)(r + base + 4);
    float x[8] = {xa.x + ra.x, xa.y + ra.y, xa.z + ra.z, xa.w + ra.w,
                  xb.x + rb.x, xb.y + rb.y, xb.z + rb.z, xb.w + rb.w};

    float s = 0.f;
#pragma unroll
    for (int i = 0; i < 8; i++) s += x[i];
#pragma unroll
    for (int o = 16; o > 0; o >>= 1) s += __shfl_xor_sync(0xffffffffu, s, o);
    float mu = s * (1.f / 256.f);

    float vsum = 0.f;
#pragma unroll
    for (int i = 0; i < 8; i++) {
        x[i] -= mu;
        vsum = fmaf(x[i], x[i], vsum);
    }
#pragma unroll
    for (int o = 16; o > 0; o >>= 1) vsum += __shfl_xor_sync(0xffffffffu, vsum, o);
    float rstd = rsqrtf(vsum * (1.f / 256.f) + 1e-5f);

    float4 ga = *(const float4*)(g + lane * 8);
    float4 gb = *(const float4*)(g + lane * 8 + 4);
    float4 ba = *(const float4*)(bb + lane * 8);
    float4 b4 = *(const float4*)(bb + lane * 8 + 4);

    float y[8];
    y[0] = x[0] * rstd * ga.x + ba.x;
    y[1] = x[1] * rstd * ga.y + ba.y;
    y[2] = x[2] * rstd * ga.z + ba.z;
    y[3] = x[3] * rstd * ga.w + ba.w;
    y[4] = x[4] * rstd * gb.x + b4.x;
    y[5] = x[5] * rstd * gb.y + b4.y;
    y[6] = x[6] * rstd * gb.z + b4.z;
    y[7] = x[7] * rstd * gb.w + b4.w;
    *(float4*)(out + base)     = make_float4(y[0], y[1], y[2], y[3]);
    *(float4*)(out + base + 4) = make_float4(y[4], y[5], y[6], y[7]);

    if (hi) {
        uint32_t hw[4], lw[4];
#pragma unroll
        for (int i = 0; i < 4; i++)
            split2(y[2 * i], y[2 * i + 1], hw[i], lw[i]);
        *(uint4*)(hi + base) = make_uint4(hw[0], hw[1], hw[2], hw[3]);
        *(uint4*)(lo + base) = make_uint4(lw[0], lw[1], lw[2], lw[3]);
    }
}

// ---------------- launch ----------------------------------------------------
extern "C" void kernel_launch(void* const* d_in, const int* in_sizes, int n_in,
                              void* d_out, int out_size)
{
    const float* x    = (const float*)d_in[0];
    const int*   mask = (const int*)d_in[1];
    const float* Win = (const float*)d_in[2];
    const float* bin = (const float*)d_in[3];
    const float* Wq  = (const float*)d_in[4];
    const float* bq  = (const float*)d_in[5];
    const float* Wk  = (const float*)d_in[6];
    const float* bk  = (const float*)d_in[7];
    const float* Wv  = (const float*)d_in[8];
    const float* bv  = (const float*)d_in[9];
    const float* Wo  = (const float*)d_in[10];
    const float* bo  = (const float*)d_in[11];
    const float* g1  = (const float*)d_in[12];
    const float* b1  = (const float*)d_in[13];
    const float* W1  = (const float*)d_in[14];
    const float* c1  = (const float*)d_in[15];
    const float* W2  = (const float*)d_in[16];
    const float* c2  = (const float*)d_in[17];
    const float* g2  = (const float*)d_in[18];
    const float* b2  = (const float*)d_in[19];
    float* out = (float*)d_out;

    float *h, *r, *r2, *bqkv;
    uint16_t *qkvh, *ahi, *alo, *bhi, *blo, *whi, *wlo;
    cudaGetSymbolAddress((void**)&h,    g_h);
    cudaGetSymbolAddress((void**)&r,    g_r);
    cudaGetSymbolAddress((void**)&r2,   g_r2);
    cudaGetSymbolAddress((void**)&qkvh, g_qkvh);
    cudaGetSymbolAddress((void**)&bqkv, g_bqkv);
    cudaGetSymbolAddress((void**)&ahi,  g_ahi);
    cudaGetSymbolAddress((void**)&alo,  g_alo);
    cudaGetSymbolAddress((void**)&bhi,  g_bhi);
    cudaGetSymbolAddress((void**)&blo,  g_blo);
    cudaGetSymbolAddress((void**)&whi,  g_whi);
    cudaGetSymbolAddress((void**)&wlo,  g_wlo);

    cudaFuncSetAttribute(attn_kernel,
                         cudaFuncAttributeMaxDynamicSharedMemorySize,
                         ATTN_SMEM);
    cudaFuncSetAttribute(hgemm_kernel,
                         cudaFuncAttributeMaxDynamicSharedMemorySize,
                         HG_SMEM);

    // ---- prep (2 launches) ----
    wsplit_all_kernel<<<2304, 256>>>(Wq, Wk, Wv, Wo, W1, W2, whi, wlo);
    bpack_kernel<<<NLAYER, QKVN>>>(bq, bk, bv, bqkv);

    inproj_kernel<<<MTOK, 256>>>(x, Win, bin, h, ahi, alo);

    dim3 gQKV(QKVN / 128, 128);
    dim3 gD(2, 128);
    dim3 gF(8, 128);
    const int lnGrid = MTOK / 8;

    for (int l = 0; l < NLAYER; l++) {
        size_t wo = (size_t)l * WPL;

        // fused QKV projection (hi*hi only), bf16-packed output
        hgemm_kernel<<<gQKV, 256, HG_SMEM>>>(ahi, nullptr,
            whi + wo, wlo + wo, bqkv + l * QKVN,
            nullptr, qkvh, nullptr, MTOK, QKVN, DMODEL, 0, 1);

        // attention -> packed bf16 output into ahi
        attn_kernel<<<32 * NHEAD, 512, ATTN_SMEM>>>(qkvh, mask, ahi);

        // Wo projection: A single-bf16, B hi/lo (prods=2)
        hgemm_kernel<<<gD, 256, HG_SMEM>>>(ahi, nullptr,
            whi + wo + 196608, wlo + wo + 196608, bo + l * DMODEL,
            r, nullptr, nullptr, MTOK, DMODEL, DMODEL, 0, 2);
        add_ln_kernel<<<lnGrid, 256>>>(h, r, g1 + l * DMODEL, b1 + l * DMODEL,
                                       h, ahi, alo);

        // FFN: W1 prods=3 (A hi/lo), split output; W2 prods=3 (A hi/lo)
        hgemm_kernel<<<gF, 256, HG_SMEM>>>(ahi, alo,
            whi + wo + 262144, wlo + wo + 262144, c1 + l * FFDIM,
            nullptr, bhi, blo, MTOK, FFDIM, DMODEL, 1, 3);
        hgemm_kernel<<<gD, 256, HG_SMEM>>>(bhi, blo,
            whi + wo + 524288, wlo + wo + 524288, c2 + l * DMODEL,
            r2, nullptr, nullptr, MTOK, DMODEL, FFDIM, 0, 3);

        float* dst = (l == NLAYER - 1) ? out : h;
        uint16_t* nhi = (l == NLAYER - 1) ? nullptr : ahi;
        uint16_t* nlo = (l == NLAYER - 1) ? nullptr : alo;
        add_ln_kernel<<<lnGrid, 256>>>(h, r2, g2 + l * DMODEL, b2 + l * DMODEL,
                                       dst, nhi, nlo);
    }
}